// round 5
// baseline (speedup 1.0000x reference)
#include <cuda_runtime.h>
#include <cstdint>

// Problem constants (fixed by the reference)
#define NSLOT 1048576u      // N
#define WDIM  64            // W
#define EPSF  1e-8f

#define HIST_BUCKETS 2048   // u in [0,1) -> bucket = float_bits(u)>>19 in [0, 2032]
#define HIST_SHIFT   19
#define SORT_CAP     8192   // max gathered candidates
#define KSEL         64     // minimum number of smallest elements to gather

#define COS_BLOCKS   (NSLOT / 256)        // 4096, thread-per-row output
#define ELEM_BLOCKS  (NSLOT / 1024)       // 1024, 4 rows per thread
#define P2_BLOCKS    (NSLOT / 1024)       // 1024, 4 floats per thread

// ---------------- scratch (device globals; no allocations allowed) ------------
__device__ float              g_partial_sum[COS_BLOCKS];
__device__ unsigned           g_hist[HIST_BUCKETS];
__device__ float              g_inv_sum;
__device__ unsigned           g_thresh;   // gathered iff float_bits(usage) < g_thresh
__device__ unsigned           g_count;
__device__ unsigned long long g_pairs[SORT_CAP];
__device__ float              g_scale2;   // beta * log2(e) / max(||key||, eps)
__device__ float              g_beta2;    // beta * log2(e)   (softmax shift)

// ---------------- helpers ------------------------------------------------------
__device__ __forceinline__ float warp_sum(float v) {
    #pragma unroll
    for (int o = 16; o; o >>= 1) v += __shfl_xor_sync(0xffffffffu, v, o);
    return v;
}
__device__ __forceinline__ float rsqrt_approx(float x) {
    float r; asm("rsqrt.approx.f32 %0, %1;" : "=f"(r) : "f"(x)); return r;
}
__device__ __forceinline__ float ex2_approx(float x) {
    float r; asm("ex2.approx.f32 %0, %1;" : "=f"(r) : "f"(x)); return r;
}

// ---------------- kernels ------------------------------------------------------

// 1 block, 256 threads: zero hist/count, compute key norm scale + shift (log2 domain).
__global__ void k_prep(const float* __restrict__ key, const float* __restrict__ beta) {
    const int t = threadIdx.x;
    #pragma unroll
    for (int i = 0; i < HIST_BUCKETS / 256; i++) g_hist[t + i * 256] = 0u;
    if (t == 0) g_count = 0u;
    if (t < 32) {
        float a = key[t], b = key[t + 32];
        float s = warp_sum(a * a + b * b);
        if (t == 0) {
            float kn = fmaxf(sqrtf(s), EPSF);
            float bv = beta[0];
            g_scale2 = bv * 1.44269504088896f / kn;
            g_beta2  = bv * 1.44269504088896f;
        }
    }
}

// Cosine pass only. Warp owns 32 rows; iteration j loads 4 rows (1KB contiguous,
// 32B per lane), reduces with a 3-step butterfly inside 8-lane groups + 1 idx
// shuffle for ownership (2 SHFL/row). 2-deep software pipeline keeps regs low.
//   out[0..N) = exp(sim*beta - beta)   (unnormalized content weighting)
// plus per-block sums of e.
__global__ void __launch_bounds__(256) k_cos(
    const float* __restrict__ mem, const float* __restrict__ key,
    float* __restrict__ out)
{
    __shared__ float ssum[8];
    const int t = threadIdx.x, lane = t & 31, warp = t >> 5;

    const float4* key4 = reinterpret_cast<const float4*>(key);
    const float4 kc0 = key4[2 * (lane & 7)];
    const float4 kc1 = key4[2 * (lane & 7) + 1];

    const unsigned rowbase = blockIdx.x * 256u + (unsigned)(warp * 32);
    const float4* g = reinterpret_cast<const float4*>(mem) + (size_t)rowbase * 16;

    float my_d = 0.0f, my_n = 0.0f;
    float4 v0 = g[lane * 2], v1 = g[lane * 2 + 1];

    #pragma unroll
    for (int j = 0; j < 8; j++) {
        float4 p0, p1;
        if (j < 7) { p0 = g[(j + 1) * 64 + lane * 2]; p1 = g[(j + 1) * 64 + lane * 2 + 1]; }
        float d = v0.x * kc0.x + v0.y * kc0.y + v0.z * kc0.z + v0.w * kc0.w
                + v1.x * kc1.x + v1.y * kc1.y + v1.z * kc1.z + v1.w * kc1.w;
        float n = v0.x * v0.x + v0.y * v0.y + v0.z * v0.z + v0.w * v0.w
                + v1.x * v1.x + v1.y * v1.y + v1.z * v1.z + v1.w * v1.w;
        #pragma unroll
        for (int o = 4; o; o >>= 1) {          // butterfly within 8-lane groups
            d += __shfl_xor_sync(0xffffffffu, d, o);
            n += __shfl_xor_sync(0xffffffffu, n, o);
        }
        // owner lane 4j+g fetches from lane g*8 (g = lane&3 for owners)
        float od = __shfl_sync(0xffffffffu, d, (lane & 3) * 8);
        float on = __shfl_sync(0xffffffffu, n, (lane & 3) * 8);
        if ((lane >> 2) == j) { my_d = od; my_n = on; }
        v0 = p0; v1 = p1;
    }

    const unsigned i = blockIdx.x * 256u + (unsigned)t;
    float rs = rsqrt_approx(fmaxf(my_n, 1e-16f));           // 1/max(||row||,1e-8)
    float e  = ex2_approx(my_d * rs * g_scale2 - g_beta2);  // exp(sim*b - b) in (0,1]
    out[i] = e;

    float s = warp_sum(e);
    if (lane == 0) ssum[warp] = s;
    __syncthreads();
    if (t == 0) {
        float tot = ssum[0];
        #pragma unroll
        for (int j = 1; j < 8; j++) tot += ssum[j];
        g_partial_sum[blockIdx.x] = tot;
    }
}

// Elementwise pass: retention, usage, allocation-zero, histogram. 4 rows/thread.
__global__ void __launch_bounds__(256) k_elem(
    const float* __restrict__ fg, const float* __restrict__ rw,
    const float* __restrict__ pu, const float* __restrict__ ww,
    float* __restrict__ out)
{
    const unsigned q = blockIdx.x * 256u + threadIdx.x;     // float4 row-group index
    const float4 f = *reinterpret_cast<const float4*>(fg);
    const float4* rw4 = reinterpret_cast<const float4*>(rw);
    float4 r0 = rw4[4 * q], r1 = rw4[4 * q + 1], r2 = rw4[4 * q + 2], r3 = rw4[4 * q + 3];
    float4 p = reinterpret_cast<const float4*>(pu)[q];
    float4 w = reinterpret_cast<const float4*>(ww)[q];

    float4 ret;
    ret.x = (1.f - r0.x * f.x) * (1.f - r0.y * f.y) * (1.f - r0.z * f.z) * (1.f - r0.w * f.w);
    ret.y = (1.f - r1.x * f.x) * (1.f - r1.y * f.y) * (1.f - r1.z * f.z) * (1.f - r1.w * f.w);
    ret.z = (1.f - r2.x * f.x) * (1.f - r2.y * f.y) * (1.f - r2.z * f.z) * (1.f - r2.w * f.w);
    ret.w = (1.f - r3.x * f.x) * (1.f - r3.y * f.y) * (1.f - r3.z * f.z) * (1.f - r3.w * f.w);

    float4 u;
    u.x = (p.x + w.x - p.x * w.x) * ret.x;
    u.y = (p.y + w.y - p.y * w.y) * ret.y;
    u.z = (p.z + w.z - p.z * w.z) * ret.z;
    u.w = (p.w + w.w - p.w * w.w) * ret.w;

    reinterpret_cast<float4*>(out + NSLOT)[q]      = ret;
    reinterpret_cast<float4*>(out + 2u * NSLOT)[q] = u;
    reinterpret_cast<float4*>(out + 3u * NSLOT)[q] = make_float4(0.f, 0.f, 0.f, 0.f);

    const int lane = threadIdx.x & 31;
    #pragma unroll
    for (int c = 0; c < 4; c++) {
        float uv = (c == 0) ? u.x : (c == 1) ? u.y : (c == 2) ? u.z : u.w;
        unsigned b = __float_as_uint(uv) >> HIST_SHIFT;
        if (b >= HIST_BUCKETS) b = HIST_BUCKETS - 1;
        unsigned peers = __match_any_sync(0xffffffffu, b);
        if (lane == __ffs(peers) - 1) atomicAdd(&g_hist[b], (unsigned)__popc(peers));
    }
}

// 1 block, 1024 threads: reduce partial sums -> 1/sum; pick gather threshold
// from histogram (first bucket covering >= KSEL smallest, capped at SORT_CAP).
__global__ void k_mid() {
    const int t = threadIdx.x;
    __shared__ float sm[32];

    float s = 0.0f;
    #pragma unroll
    for (int j = 0; j < COS_BLOCKS / 1024; j++) s += g_partial_sum[t + j * 1024];
    s = warp_sum(s);
    int lane = t & 31, warp = t >> 5;
    if (lane == 0) sm[warp] = s;
    __syncthreads();
    if (t < 32) {
        float v = sm[t];
        v = warp_sum(v);
        if (t == 0) g_inv_sum = 1.0f / v;
    }

    __shared__ unsigned tsum[1024];
    __shared__ int sT1, sT2;
    unsigned l0 = g_hist[t * 2], l1 = g_hist[t * 2 + 1];
    tsum[t] = l0 + l1;
    if (t == 0) { sT1 = HIST_BUCKETS - 1; sT2 = 0x7fffffff; }
    __syncthreads();
    for (int off = 1; off < 1024; off <<= 1) {
        unsigned v = (t >= off) ? tsum[t - off] : 0u;
        __syncthreads();
        tsum[t] += v;
        __syncthreads();
    }
    unsigned cum = (t == 0) ? 0u : tsum[t - 1];
    cum += l0;
    if (cum >= KSEL)    atomicMin(&sT1, t * 2);
    if (cum > SORT_CAP) atomicMin(&sT2, t * 2);
    cum += l1;
    if (cum >= KSEL)    atomicMin(&sT1, t * 2 + 1);
    if (cum > SORT_CAP) atomicMin(&sT2, t * 2 + 1);
    __syncthreads();
    if (t == 0) {
        int T = sT1;
        if (sT2 != 0x7fffffff && sT2 - 1 < T) T = sT2 - 1;
        if (T < 0) T = 0;
        g_thresh = ((unsigned)(T + 1)) << HIST_SHIFT;
    }
}

// Normalize content weighting + gather smallest usages (float4 per thread).
__global__ void __launch_bounds__(256) k_pass2(float* __restrict__ out) {
    const unsigned q = blockIdx.x * 256u + threadIdx.x;     // float4 index
    float4* o4 = reinterpret_cast<float4*>(out);
    float4 e = o4[q];
    float4 u = o4[(2u * NSLOT) / 4 + q];
    const float inv = g_inv_sum;
    e.x *= inv; e.y *= inv; e.z *= inv; e.w *= inv;
    o4[q] = e;

    const unsigned th = g_thresh;
    const unsigned base = q * 4u;
    #pragma unroll
    for (int c = 0; c < 4; c++) {
        float uv = (c == 0) ? u.x : (c == 1) ? u.y : (c == 2) ? u.z : u.w;
        if (__float_as_uint(uv) < th) {
            unsigned pos = atomicAdd(&g_count, 1u);
            if (pos < SORT_CAP)
                g_pairs[pos] = ((unsigned long long)__float_as_uint(uv) << 32)
                             | (unsigned long long)(base + c);
        }
    }
}

// Single block: bitonic sort (dynamic power-of-two size) of (usage_bits:index)
// pairs -- 64-bit key gives the stable order of jnp argsort -- then serial
// cumprod with early exit once the product underflows to exactly 0.
__global__ void k_sortalloc(float* __restrict__ out) {
    extern __shared__ unsigned long long sp[];
    const unsigned count = min(g_count, (unsigned)SORT_CAP);
    unsigned n = 2;
    while (n < count) n <<= 1;

    const int t = threadIdx.x;
    for (unsigned i = t; i < n; i += 1024)
        sp[i] = (i < count) ? g_pairs[i] : 0xFFFFFFFFFFFFFFFFull;
    __syncthreads();

    for (unsigned k = 2; k <= n; k <<= 1) {
        for (unsigned j = k >> 1; j > 0; j >>= 1) {
            for (unsigned i = t; i < n; i += 1024) {
                unsigned ixj = i ^ j;
                if (ixj > i) {
                    bool up = ((i & k) == 0);
                    unsigned long long a = sp[i], b = sp[ixj];
                    if ((a > b) == up) { sp[i] = b; sp[ixj] = a; }
                }
            }
            __syncthreads();
        }
    }

    if (t == 0) {
        float prod = 1.0f, prev = 0.0f;
        for (unsigned j = 0; j < count; j++) {
            unsigned long long p = sp[j];
            float    sv  = __uint_as_float((unsigned)(p >> 32));
            unsigned idx = (unsigned)(p & 0xFFFFFFFFull);
            float a = (j == 0) ? (1.0f - sv) : (1.0f - prev) * prod;
            out[3u * NSLOT + idx] = a;
            prod *= sv;
            prev  = sv;
            if (prod == 0.0f) break;   // remaining allocations are exactly 0
        }
    }
}

// ---------------- launch --------------------------------------------------------
extern "C" void kernel_launch(void* const* d_in, const int* in_sizes, int n_in,
                              void* d_out, int out_size)
{
    const float* key  = (const float*)d_in[0];  // desired_content (64)
    const float* mem  = (const float*)d_in[1];  // memory (N*W)
    const float* beta = (const float*)d_in[2];  // key_strength (1)
    const float* fg   = (const float*)d_in[3];  // free_gate (4)
    const float* rw   = (const float*)d_in[4];  // read_weighting (N*4)
    const float* pu   = (const float*)d_in[5];  // previous_usage (N)
    const float* ww   = (const float*)d_in[6];  // write_weighting (N)
    float* out = (float*)d_out;                 // (4, N) float32

    cudaFuncSetAttribute(k_sortalloc, cudaFuncAttributeMaxDynamicSharedMemorySize,
                         SORT_CAP * (int)sizeof(unsigned long long));

    k_prep      <<<1, 256>>>(key, beta);
    k_cos       <<<COS_BLOCKS, 256>>>(mem, key, out);
    k_elem      <<<ELEM_BLOCKS, 256>>>(fg, rw, pu, ww, out);
    k_mid       <<<1, 1024>>>();
    k_pass2     <<<P2_BLOCKS, 256>>>(out);
    k_sortalloc <<<1, 1024, SORT_CAP * (int)sizeof(unsigned long long)>>>(out);
}

// round 6
// speedup vs baseline: 1.0058x; 1.0058x over previous
#include <cuda_runtime.h>
#include <cstdint>

// Problem constants (fixed by the reference)
#define NSLOT 1048576u      // N
#define WDIM  64            // W
#define EPSF  1e-8f

#define HIST_BUCKETS 2048   // u in [0,1) -> bucket = float_bits(u)>>19 in [0, 2032]
#define HIST_SHIFT   19
#define SORT_CAP     8192   // max gathered candidates
#define KSEL         64     // minimum number of smallest elements to gather

#define COS_BLOCKS   (NSLOT / 256)        // 4096, thread-per-row output
#define ELEM_BLOCKS  (NSLOT / 1024)       // 1024, 4 rows per thread
#define P2_BLOCKS    (NSLOT / 1024)       // 1024, 4 floats per thread

// ---------------- scratch (device globals; no allocations allowed) ------------
__device__ float              g_partial_sum[COS_BLOCKS];
__device__ unsigned           g_hist[HIST_BUCKETS];
__device__ float              g_inv_sum;
__device__ unsigned           g_thresh;   // gathered iff float_bits(usage) < g_thresh
__device__ unsigned           g_count;
__device__ unsigned long long g_pairs[SORT_CAP];
__device__ float              g_scale2;   // beta * log2(e) / max(||key||, eps)
__device__ float              g_beta2;    // beta * log2(e)   (softmax shift)

// ---------------- helpers ------------------------------------------------------
__device__ __forceinline__ float warp_sum(float v) {
    #pragma unroll
    for (int o = 16; o; o >>= 1) v += __shfl_xor_sync(0xffffffffu, v, o);
    return v;
}
__device__ __forceinline__ float rsqrt_approx(float x) {
    float r; asm("rsqrt.approx.f32 %0, %1;" : "=f"(r) : "f"(x)); return r;
}
__device__ __forceinline__ float ex2_approx(float x) {
    float r; asm("ex2.approx.f32 %0, %1;" : "=f"(r) : "f"(x)); return r;
}

// ---------------- kernels ------------------------------------------------------

// 1 block, 256 threads: zero hist/count, compute key norm scale + shift (log2 domain).
__global__ void k_prep(const float* __restrict__ key, const float* __restrict__ beta) {
    const int t = threadIdx.x;
    #pragma unroll
    for (int i = 0; i < HIST_BUCKETS / 256; i++) g_hist[t + i * 256] = 0u;
    if (t == 0) g_count = 0u;
    if (t < 32) {
        float a = key[t], b = key[t + 32];
        float s = warp_sum(a * a + b * b);
        if (t == 0) {
            float kn = fmaxf(sqrtf(s), EPSF);
            float bv = beta[0];
            g_scale2 = bv * 1.44269504088896f / kn;
            g_beta2  = bv * 1.44269504088896f;
        }
    }
}

// Cosine pass only. Warp owns 32 rows; iteration j loads 4 rows (1KB contiguous,
// 32B per lane), reduces with a 3-step butterfly inside 8-lane groups + 1 idx
// shuffle for ownership (2 SHFL/row). 2-deep software pipeline keeps regs low.
//   out[0..N) = exp(sim*beta - beta)   (unnormalized content weighting)
// plus per-block sums of e.
__global__ void __launch_bounds__(256) k_cos(
    const float* __restrict__ mem, const float* __restrict__ key,
    float* __restrict__ out)
{
    __shared__ float ssum[8];
    const int t = threadIdx.x, lane = t & 31, warp = t >> 5;

    const float4* key4 = reinterpret_cast<const float4*>(key);
    const float4 kc0 = key4[2 * (lane & 7)];
    const float4 kc1 = key4[2 * (lane & 7) + 1];

    const unsigned rowbase = blockIdx.x * 256u + (unsigned)(warp * 32);
    const float4* g = reinterpret_cast<const float4*>(mem) + (size_t)rowbase * 16;

    float my_d = 0.0f, my_n = 0.0f;
    float4 v0 = g[lane * 2], v1 = g[lane * 2 + 1];

    #pragma unroll
    for (int j = 0; j < 8; j++) {
        float4 p0, p1;
        if (j < 7) { p0 = g[(j + 1) * 64 + lane * 2]; p1 = g[(j + 1) * 64 + lane * 2 + 1]; }
        float d = v0.x * kc0.x + v0.y * kc0.y + v0.z * kc0.z + v0.w * kc0.w
                + v1.x * kc1.x + v1.y * kc1.y + v1.z * kc1.z + v1.w * kc1.w;
        float n = v0.x * v0.x + v0.y * v0.y + v0.z * v0.z + v0.w * v0.w
                + v1.x * v1.x + v1.y * v1.y + v1.z * v1.z + v1.w * v1.w;
        #pragma unroll
        for (int o = 4; o; o >>= 1) {          // butterfly within 8-lane groups
            d += __shfl_xor_sync(0xffffffffu, d, o);
            n += __shfl_xor_sync(0xffffffffu, n, o);
        }
        // owner lane 4j+g fetches from lane g*8 (g = lane&3 for owners)
        float od = __shfl_sync(0xffffffffu, d, (lane & 3) * 8);
        float on = __shfl_sync(0xffffffffu, n, (lane & 3) * 8);
        if ((lane >> 2) == j) { my_d = od; my_n = on; }
        v0 = p0; v1 = p1;
    }

    const unsigned i = blockIdx.x * 256u + (unsigned)t;
    float rs = rsqrt_approx(fmaxf(my_n, 1e-16f));           // 1/max(||row||,1e-8)
    float e  = ex2_approx(my_d * rs * g_scale2 - g_beta2);  // exp(sim*b - b) in (0,1]
    out[i] = e;

    float s = warp_sum(e);
    if (lane == 0) ssum[warp] = s;
    __syncthreads();
    if (t == 0) {
        float tot = ssum[0];
        #pragma unroll
        for (int j = 1; j < 8; j++) tot += ssum[j];
        g_partial_sum[blockIdx.x] = tot;
    }
}

// Elementwise pass: retention, usage, allocation-zero, histogram. 4 rows/thread.
__global__ void __launch_bounds__(256) k_elem(
    const float* __restrict__ fg, const float* __restrict__ rw,
    const float* __restrict__ pu, const float* __restrict__ ww,
    float* __restrict__ out)
{
    const unsigned q = blockIdx.x * 256u + threadIdx.x;     // float4 row-group index
    const float4 f = *reinterpret_cast<const float4*>(fg);
    const float4* rw4 = reinterpret_cast<const float4*>(rw);
    float4 r0 = rw4[4 * q], r1 = rw4[4 * q + 1], r2 = rw4[4 * q + 2], r3 = rw4[4 * q + 3];
    float4 p = reinterpret_cast<const float4*>(pu)[q];
    float4 w = reinterpret_cast<const float4*>(ww)[q];

    float4 ret;
    ret.x = (1.f - r0.x * f.x) * (1.f - r0.y * f.y) * (1.f - r0.z * f.z) * (1.f - r0.w * f.w);
    ret.y = (1.f - r1.x * f.x) * (1.f - r1.y * f.y) * (1.f - r1.z * f.z) * (1.f - r1.w * f.w);
    ret.z = (1.f - r2.x * f.x) * (1.f - r2.y * f.y) * (1.f - r2.z * f.z) * (1.f - r2.w * f.w);
    ret.w = (1.f - r3.x * f.x) * (1.f - r3.y * f.y) * (1.f - r3.z * f.z) * (1.f - r3.w * f.w);

    float4 u;
    u.x = (p.x + w.x - p.x * w.x) * ret.x;
    u.y = (p.y + w.y - p.y * w.y) * ret.y;
    u.z = (p.z + w.z - p.z * w.z) * ret.z;
    u.w = (p.w + w.w - p.w * w.w) * ret.w;

    reinterpret_cast<float4*>(out + NSLOT)[q]      = ret;
    reinterpret_cast<float4*>(out + 2u * NSLOT)[q] = u;
    reinterpret_cast<float4*>(out + 3u * NSLOT)[q] = make_float4(0.f, 0.f, 0.f, 0.f);

    const int lane = threadIdx.x & 31;
    #pragma unroll
    for (int c = 0; c < 4; c++) {
        float uv = (c == 0) ? u.x : (c == 1) ? u.y : (c == 2) ? u.z : u.w;
        unsigned b = __float_as_uint(uv) >> HIST_SHIFT;
        if (b >= HIST_BUCKETS) b = HIST_BUCKETS - 1;
        unsigned peers = __match_any_sync(0xffffffffu, b);
        if (lane == __ffs(peers) - 1) atomicAdd(&g_hist[b], (unsigned)__popc(peers));
    }
}

// 1 block, 1024 threads: reduce partial sums -> 1/sum; pick gather threshold
// from histogram (first bucket covering >= KSEL smallest, capped at SORT_CAP).
__global__ void k_mid() {
    const int t = threadIdx.x;
    __shared__ float sm[32];

    float s = 0.0f;
    #pragma unroll
    for (int j = 0; j < COS_BLOCKS / 1024; j++) s += g_partial_sum[t + j * 1024];
    s = warp_sum(s);
    int lane = t & 31, warp = t >> 5;
    if (lane == 0) sm[warp] = s;
    __syncthreads();
    if (t < 32) {
        float v = sm[t];
        v = warp_sum(v);
        if (t == 0) g_inv_sum = 1.0f / v;
    }

    __shared__ unsigned tsum[1024];
    __shared__ int sT1, sT2;
    unsigned l0 = g_hist[t * 2], l1 = g_hist[t * 2 + 1];
    tsum[t] = l0 + l1;
    if (t == 0) { sT1 = HIST_BUCKETS - 1; sT2 = 0x7fffffff; }
    __syncthreads();
    for (int off = 1; off < 1024; off <<= 1) {
        unsigned v = (t >= off) ? tsum[t - off] : 0u;
        __syncthreads();
        tsum[t] += v;
        __syncthreads();
    }
    unsigned cum = (t == 0) ? 0u : tsum[t - 1];
    cum += l0;
    if (cum >= KSEL)    atomicMin(&sT1, t * 2);
    if (cum > SORT_CAP) atomicMin(&sT2, t * 2);
    cum += l1;
    if (cum >= KSEL)    atomicMin(&sT1, t * 2 + 1);
    if (cum > SORT_CAP) atomicMin(&sT2, t * 2 + 1);
    __syncthreads();
    if (t == 0) {
        int T = sT1;
        if (sT2 != 0x7fffffff && sT2 - 1 < T) T = sT2 - 1;
        if (T < 0) T = 0;
        g_thresh = ((unsigned)(T + 1)) << HIST_SHIFT;
    }
}

// Normalize content weighting + gather smallest usages (float4 per thread).
__global__ void __launch_bounds__(256) k_pass2(float* __restrict__ out) {
    const unsigned q = blockIdx.x * 256u + threadIdx.x;     // float4 index
    float4* o4 = reinterpret_cast<float4*>(out);
    float4 e = o4[q];
    float4 u = o4[(2u * NSLOT) / 4 + q];
    const float inv = g_inv_sum;
    e.x *= inv; e.y *= inv; e.z *= inv; e.w *= inv;
    o4[q] = e;

    const unsigned th = g_thresh;
    const unsigned base = q * 4u;
    #pragma unroll
    for (int c = 0; c < 4; c++) {
        float uv = (c == 0) ? u.x : (c == 1) ? u.y : (c == 2) ? u.z : u.w;
        if (__float_as_uint(uv) < th) {
            unsigned pos = atomicAdd(&g_count, 1u);
            if (pos < SORT_CAP)
                g_pairs[pos] = ((unsigned long long)__float_as_uint(uv) << 32)
                             | (unsigned long long)(base + c);
        }
    }
}

// Single block: bitonic sort (dynamic power-of-two size) of (usage_bits:index)
// pairs -- 64-bit key gives the stable order of jnp argsort -- then serial
// cumprod with early exit once the product underflows to exactly 0.
__global__ void k_sortalloc(float* __restrict__ out) {
    extern __shared__ unsigned long long sp[];
    const unsigned count = min(g_count, (unsigned)SORT_CAP);
    unsigned n = 2;
    while (n < count) n <<= 1;

    const int t = threadIdx.x;
    for (unsigned i = t; i < n; i += 1024)
        sp[i] = (i < count) ? g_pairs[i] : 0xFFFFFFFFFFFFFFFFull;
    __syncthreads();

    for (unsigned k = 2; k <= n; k <<= 1) {
        for (unsigned j = k >> 1; j > 0; j >>= 1) {
            for (unsigned i = t; i < n; i += 1024) {
                unsigned ixj = i ^ j;
                if (ixj > i) {
                    bool up = ((i & k) == 0);
                    unsigned long long a = sp[i], b = sp[ixj];
                    if ((a > b) == up) { sp[i] = b; sp[ixj] = a; }
                }
            }
            __syncthreads();
        }
    }

    if (t == 0) {
        float prod = 1.0f, prev = 0.0f;
        for (unsigned j = 0; j < count; j++) {
            unsigned long long p = sp[j];
            float    sv  = __uint_as_float((unsigned)(p >> 32));
            unsigned idx = (unsigned)(p & 0xFFFFFFFFull);
            float a = (j == 0) ? (1.0f - sv) : (1.0f - prev) * prod;
            out[3u * NSLOT + idx] = a;
            prod *= sv;
            prev  = sv;
            if (prod == 0.0f) break;   // remaining allocations are exactly 0
        }
    }
}

// ---------------- launch --------------------------------------------------------
extern "C" void kernel_launch(void* const* d_in, const int* in_sizes, int n_in,
                              void* d_out, int out_size)
{
    const float* key  = (const float*)d_in[0];  // desired_content (64)
    const float* mem  = (const float*)d_in[1];  // memory (N*W)
    const float* beta = (const float*)d_in[2];  // key_strength (1)
    const float* fg   = (const float*)d_in[3];  // free_gate (4)
    const float* rw   = (const float*)d_in[4];  // read_weighting (N*4)
    const float* pu   = (const float*)d_in[5];  // previous_usage (N)
    const float* ww   = (const float*)d_in[6];  // write_weighting (N)
    float* out = (float*)d_out;                 // (4, N) float32

    cudaFuncSetAttribute(k_sortalloc, cudaFuncAttributeMaxDynamicSharedMemorySize,
                         SORT_CAP * (int)sizeof(unsigned long long));

    k_prep      <<<1, 256>>>(key, beta);
    k_cos       <<<COS_BLOCKS, 256>>>(mem, key, out);
    k_elem      <<<ELEM_BLOCKS, 256>>>(fg, rw, pu, ww, out);
    k_mid       <<<1, 1024>>>();
    k_pass2     <<<P2_BLOCKS, 256>>>(out);
    k_sortalloc <<<1, 1024, SORT_CAP * (int)sizeof(unsigned long long)>>>(out);
}